// round 15
// baseline (speedup 1.0000x reference)
#include <cuda_runtime.h>
#include <cuda_fp16.h>

#define HH 2048
#define WW 2048
#define HWN (HH*WW)
#define W4 (WW/4)
#define HW4 (HWN/4)
#define NCTA 148
#define NTHR 256
#define MAXR 14
#define FB 2048

// dyn smem: s_im 57344 + s_rm 57344 + s_ch 1KB + s_cdf 1KB + s_fh 8KB = 124928B
#define SMEM_BYTES (MAXR*512*8*2 + 1024 + 1024 + FB*4)

__device__ double g_sums[4];
__device__ unsigned int g_fhist[FB];
__device__ int g_minbits;          // starts 0 (module load); treated as "unset" -> init below
__device__ int g_maxbits;
__device__ unsigned int g_bar1;
__device__ unsigned int g_bar2;
// NOTE on init: device globals are zero at module load. We keep the invariant
// that every launch leaves all globals zeroed (g_minbits zeroed too; we bias it).

__device__ __forceinline__ int q8(float x) {
    return __float2int_rd(__saturatef(x) * 255.0f);
}
__device__ __forceinline__ int grayi(int q0, int q1, int q2) {
    return (19595 * q0 + 38470 * q1 + 7471 * q2 + 32768) >> 16;
}
__device__ __forceinline__ unsigned packh2(float a, float b) {
    __half2 h = __floats2half2_rn(a, b);
    return *reinterpret_cast<unsigned*>(&h);
}
__device__ __forceinline__ float2 unpackh2(unsigned u) {
    __half2 h = *reinterpret_cast<__half2*>(&u);
    return __half22float2(h);
}

__device__ __forceinline__ float interp1p(float x, float gmin, float scale, const float2* cdfp) {
    float u = fmaxf((x - gmin) * scale, 0.0f);
    int k = min((int)u, 255);
    float2 p = cdfp[k];
    return fmaf(p.y - p.x, u - (float)k, p.x);
}

struct Row { float4 a0, a1, a2, b0, b1, b2, lv; };
struct ColSt { int gx, gy, gz, gw; float4 lP; };

__device__ __forceinline__ Row load_row(const float4* __restrict__ in,
                                        const float4* __restrict__ Rp,
                                        const float4* __restrict__ Lp, int idx) {
    Row r;
    r.a0 = __ldcs(&in[idx]); r.a1 = __ldcs(&in[idx + HW4]); r.a2 = __ldcs(&in[idx + 2 * HW4]);
    r.b0 = __ldcs(&Rp[idx]); r.b1 = __ldcs(&Rp[idx + HW4]); r.b2 = __ldcs(&Rp[idx + 2 * HW4]);
    r.lv = __ldcs(&Lp[idx]);
    return r;
}

__global__ __launch_bounds__(NTHR, 1) void kmain(const float4* __restrict__ in,
                                                 const float4* __restrict__ Rp,
                                                 const float4* __restrict__ Lp,
                                                 float* __restrict__ out) {
    extern __shared__ char sm[];
    uint2*    s_im  = (uint2*)sm;
    uint2*    s_rm  = (uint2*)(sm + MAXR*512*8);
    unsigned* s_ch  = (unsigned*)(sm + MAXR*512*16);
    float*    s_lut = (float*)s_ch;
    float*    s_cdf = (float*)(sm + MAXR*512*16 + 1024);
    unsigned* s_fh  = (unsigned*)(sm + MAXR*512*16 + 2048);
    float2*   s_cdfp = (float2*)s_fh;
    __shared__ double redd[3][8];
    __shared__ float  redf[2][8];

    const int tid = threadIdx.x;
    const int cta = blockIdx.x;

    int nr, r0;
    if (cta < 124) { nr = 14; r0 = cta * 14; }
    else           { nr = 13; r0 = 1736 + (cta - 124) * 13; }

    if (tid < 256) s_lut[tid] = __expf((float)tid * (-10.0f / 255.0f));
    for (int i = tid; i < FB; i += NTHR) s_fh[i] = 0u;
    __syncthreads();

    // ---------------- Phase 1: 2 columns/thread, depth-1 pipelined ----------------
    const int c0 = tid, c1 = tid + 256;
    ColSt st0, st1;
    if (r0 == 0) {
        st0.gx = st0.gy = st0.gz = st0.gw = 0; st0.lP = make_float4(0.f,0.f,0.f,0.f);
        st1 = st0;
    } else {
        int h0 = (r0 - 1) * W4 + c0, h1 = (r0 - 1) * W4 + c1;
        float4 b0 = __ldcs(&Rp[h0]), b1 = __ldcs(&Rp[h0 + HW4]), b2 = __ldcs(&Rp[h0 + 2*HW4]);
        st0.gx = grayi(q8(b0.x), q8(b1.x), q8(b2.x));
        st0.gy = grayi(q8(b0.y), q8(b1.y), q8(b2.y));
        st0.gz = grayi(q8(b0.z), q8(b1.z), q8(b2.z));
        st0.gw = grayi(q8(b0.w), q8(b1.w), q8(b2.w));
        st0.lP = __ldcs(&Lp[h0]);
        float4 d0 = __ldcs(&Rp[h1]), d1 = __ldcs(&Rp[h1 + HW4]), d2 = __ldcs(&Rp[h1 + 2*HW4]);
        st1.gx = grayi(q8(d0.x), q8(d1.x), q8(d2.x));
        st1.gy = grayi(q8(d0.y), q8(d1.y), q8(d2.y));
        st1.gz = grayi(q8(d0.z), q8(d1.z), q8(d2.z));
        st1.gw = grayi(q8(d0.w), q8(d1.w), q8(d2.w));
        st1.lP = __ldcs(&Lp[h1]);
    }

    float sRec = 0.f, sIs = 0.f;
    int   sRsI = 0;
    float vmin = 3.0f, vmax = -1.0f;

    Row cur0 = load_row(in, Rp, Lp, r0 * W4 + c0);
    Row cur1 = load_row(in, Rp, Lp, r0 * W4 + c1);

    auto body = [&](const Row& r, ColSt& st, int li) {
        sRec +=
            fabsf(r.b0.x * r.lv.x - r.a0.x) + fabsf(r.b0.y * r.lv.y - r.a0.y) +
            fabsf(r.b0.z * r.lv.z - r.a0.z) + fabsf(r.b0.w * r.lv.w - r.a0.w) +
            fabsf(r.b1.x * r.lv.x - r.a1.x) + fabsf(r.b1.y * r.lv.y - r.a1.y) +
            fabsf(r.b1.z * r.lv.z - r.a1.z) + fabsf(r.b1.w * r.lv.w - r.a1.w) +
            fabsf(r.b2.x * r.lv.x - r.a2.x) + fabsf(r.b2.y * r.lv.y - r.a2.y) +
            fabsf(r.b2.z * r.lv.z - r.a2.z) + fabsf(r.b2.w * r.lv.w - r.a2.w);

        float imx = fmaxf(r.a0.x, fmaxf(r.a1.x, r.a2.x));
        float imy = fmaxf(r.a0.y, fmaxf(r.a1.y, r.a2.y));
        float imz = fmaxf(r.a0.z, fmaxf(r.a1.z, r.a2.z));
        float imw = fmaxf(r.a0.w, fmaxf(r.a1.w, r.a2.w));
        float rmx = fmaxf(r.b0.x, fmaxf(r.b1.x, r.b2.x));
        float rmy = fmaxf(r.b0.y, fmaxf(r.b1.y, r.b2.y));
        float rmz = fmaxf(r.b0.z, fmaxf(r.b1.z, r.b2.z));
        float rmw = fmaxf(r.b0.w, fmaxf(r.b1.w, r.b2.w));

        s_im[li] = make_uint2(packh2(imx, imy), packh2(imz, imw));
        s_rm[li] = make_uint2(packh2(rmx, rmy), packh2(rmz, rmw));

        vmin = fminf(vmin, fminf(fminf(imx, imy), fminf(imz, imw)));
        vmax = fmaxf(vmax, fmaxf(fmaxf(imx, imy), fmaxf(imz, imw)));

        atomicAdd(&s_fh[min(FB - 1, (int)(imx * (float)FB))], 1u);
        atomicAdd(&s_fh[min(FB - 1, (int)(imy * (float)FB))], 1u);
        atomicAdd(&s_fh[min(FB - 1, (int)(imz * (float)FB))], 1u);
        atomicAdd(&s_fh[min(FB - 1, (int)(imw * (float)FB))], 1u);

        int gx = grayi(q8(r.b0.x), q8(r.b1.x), q8(r.b2.x));
        int gy = grayi(q8(r.b0.y), q8(r.b1.y), q8(r.b2.y));
        int gz = grayi(q8(r.b0.z), q8(r.b1.z), q8(r.b2.z));
        int gw = grayi(q8(r.b0.w), q8(r.b1.w), q8(r.b2.w));

        int dgx = abs(gx - st.gx), dgy = abs(gy - st.gy);
        int dgz = abs(gz - st.gz), dgw = abs(gw - st.gw);
        sRsI += dgx + dgy + dgz + dgw + 2 * (gx + gy + gz + gw);

        sIs += fabsf(r.lv.x - st.lP.x) * s_lut[dgx] + 2.0f * fabsf(r.lv.x) * s_lut[gx]
             + fabsf(r.lv.y - st.lP.y) * s_lut[dgy] + 2.0f * fabsf(r.lv.y) * s_lut[gy]
             + fabsf(r.lv.z - st.lP.z) * s_lut[dgz] + 2.0f * fabsf(r.lv.z) * s_lut[gz]
             + fabsf(r.lv.w - st.lP.w) * s_lut[dgw] + 2.0f * fabsf(r.lv.w) * s_lut[gw];

        st.gx = gx; st.gy = gy; st.gz = gz; st.gw = gw;
        st.lP = r.lv;
    };

    #pragma unroll 1
    for (int rr = 0; rr < nr - 1; rr++) {
        int nidx = (r0 + rr + 1) * W4;
        Row n0 = load_row(in, Rp, Lp, nidx + c0);
        Row n1 = load_row(in, Rp, Lp, nidx + c1);
        body(cur0, st0, rr * 512 + c0);
        body(cur1, st1, rr * 512 + c1);
        cur0 = n0; cur1 = n1;
    }
    body(cur0, st0, (nr - 1) * 512 + c0);
    body(cur1, st1, (nr - 1) * 512 + c1);

    if (r0 + nr == HH) {
        sRsI += st0.gx + st0.gy + st0.gz + st0.gw + st1.gx + st1.gy + st1.gz + st1.gw;
        sIs  += fabsf(st0.lP.x) * s_lut[st0.gx] + fabsf(st0.lP.y) * s_lut[st0.gy]
              + fabsf(st0.lP.z) * s_lut[st0.gz] + fabsf(st0.lP.w) * s_lut[st0.gw]
              + fabsf(st1.lP.x) * s_lut[st1.gx] + fabsf(st1.lP.y) * s_lut[st1.gy]
              + fabsf(st1.lP.z) * s_lut[st1.gz] + fabsf(st1.lP.w) * s_lut[st1.gw];
    }

    __syncthreads();
    for (int i = tid; i < FB; i += NTHR) {
        unsigned c = s_fh[i];
        if (c) atomicAdd(&g_fhist[i], c);
    }

    // block reduce (8 warps)
    double dRec = (double)sRec, dIs = (double)sIs;
    int    iRs = sRsI;
    const unsigned m = 0xffffffffu;
    for (int o = 16; o; o >>= 1) {
        dRec += __shfl_down_sync(m, dRec, o);
        dIs  += __shfl_down_sync(m, dIs,  o);
        iRs  += __shfl_down_sync(m, iRs,  o);
        vmin = fminf(vmin, __shfl_down_sync(m, vmin, o));
        vmax = fmaxf(vmax, __shfl_down_sync(m, vmax, o));
    }
    int lane = tid & 31, wid = tid >> 5;
    if (lane == 0) {
        redd[0][wid] = dRec; redd[1][wid] = (double)iRs; redd[2][wid] = dIs;
        redf[0][wid] = vmin; redf[1][wid] = vmax;
    }
    __syncthreads();
    if (wid == 0) {
        double dRs;
        dRec = (lane < 8) ? redd[0][lane] : 0.0;
        dRs  = (lane < 8) ? redd[1][lane] : 0.0;
        dIs  = (lane < 8) ? redd[2][lane] : 0.0;
        vmin = (lane < 8) ? redf[0][lane] : 3.0f;
        vmax = (lane < 8) ? redf[1][lane] : -1.0f;
        for (int o = 4; o; o >>= 1) {
            dRec += __shfl_down_sync(m, dRec, o);
            dRs  += __shfl_down_sync(m, dRs,  o);
            dIs  += __shfl_down_sync(m, dIs,  o);
            vmin = fminf(vmin, __shfl_down_sync(m, vmin, o));
            vmax = fmaxf(vmax, __shfl_down_sync(m, vmax, o));
        }
        if (lane == 0) {
            atomicAdd(&g_sums[0], dRec);
            atomicAdd(&g_sums[1], dRs);
            atomicAdd(&g_sums[2], dIs);
            atomicMin(&g_minbits, __float_as_int(vmin) - 0x7F800000);  // bias: rest state 0 == +inf
            atomicMax(&g_maxbits, __float_as_int(vmax));
        }
    }

    // ---- grid barrier 1 (full) ----
    __syncthreads();
    if (tid == 0) {
        __threadfence();
        atomicAdd(&g_bar1, 1u);
        while (*(volatile unsigned*)&g_bar1 < NCTA) { }
    }
    __syncthreads();
    __threadfence();

    // ---------------- Phase 3: rebin + cdf + interp + eq-sum ----------------
    const float gmin = __int_as_float(__ldcg(&g_minbits) + 0x7F800000);
    const float gmax = __int_as_float(__ldcg(&g_maxbits));
    const float scale = 256.0f / (gmax - gmin);

    if (tid < 256) s_ch[tid] = 0u;
    __syncthreads();
    for (int f = tid; f < FB; f += NTHR) {
        unsigned c = __ldcg(&g_fhist[f]);
        if (c) {
            float center = ((float)f + 0.5f) * (1.0f / (float)FB);
            int k = min(255, max(0, (int)((center - gmin) * scale)));
            atomicAdd(&s_ch[k], c);
        }
    }
    __syncthreads();

    if (tid < 256) s_cdf[tid] = (float)s_ch[tid];
    __syncthreads();
    for (int off = 1; off < 256; off <<= 1) {
        float t = 0.0f;
        if (tid < 256 && tid >= off) t = s_cdf[tid - off];
        __syncthreads();
        if (tid < 256) s_cdf[tid] += t;
        __syncthreads();
    }
    float norm = s_cdf[255];
    __syncthreads();
    if (tid < 256) s_cdf[tid] = s_cdf[tid] / norm;
    __syncthreads();
    if (tid < 256) {
        float cc0 = s_cdf[tid];
        float cc1 = (tid < 255) ? s_cdf[tid + 1] : cc0;
        s_cdfp[tid] = make_float2(cc0, cc1);
    }
    __syncthreads();

    const int nelem = nr * 512;
    float sEq = 0.f;
    for (int i = tid; i < nelem; i += NTHR) {
        uint2 u = s_im[i];
        uint2 ru = s_rm[i];
        float2 v0 = unpackh2(u.x), v1 = unpackh2(u.y);
        float2 r0f = unpackh2(ru.x), r1f = unpackh2(ru.y);
        sEq += fabsf(r0f.x - interp1p(v0.x, gmin, scale, s_cdfp))
             + fabsf(r0f.y - interp1p(v0.y, gmin, scale, s_cdfp))
             + fabsf(r1f.x - interp1p(v1.x, gmin, scale, s_cdfp))
             + fabsf(r1f.y - interp1p(v1.y, gmin, scale, s_cdfp));
    }
    double dEq = (double)sEq;
    for (int o = 16; o; o >>= 1) dEq += __shfl_down_sync(m, dEq, o);
    if (lane == 0) redd[0][wid] = dEq;
    __syncthreads();
    if (wid == 0) {
        dEq = (lane < 8) ? redd[0][lane] : 0.0;
        for (int o = 4; o; o >>= 1) dEq += __shfl_down_sync(m, dEq, o);
        if (lane == 0) atomicAdd(&g_sums[3], dEq);
    }

    // ---- finish barrier: non-leader CTAs arrive and exit; CTA0 polls ----
    __syncthreads();
    if (tid == 0) {
        __threadfence();
        atomicAdd(&g_bar2, 1u);
    }
    if (cta != 0) return;

    if (tid == 0) {
        while (*(volatile unsigned*)&g_bar2 < NCTA) { }
    }
    __syncthreads();
    __threadfence();

    // combine + full reset for next (graph-replayed) launch
    if (tid == 0) {
        double recon = __ldcg(&g_sums[0]) / (3.0 * (double)HWN);
        double denom = 2.0 * (double)(HH + 1) * (double)(WW + 2);
        double rs = __ldcg(&g_sums[1]) / (255.0 * denom);
        double is = __ldcg(&g_sums[2]) / denom;
        double eq = __ldcg(&g_sums[3]) / (double)HWN;
        out[0] = (float)(recon + 0.1 * is + 0.1 * eq + 0.01 * rs);
        g_sums[0] = 0.0; g_sums[1] = 0.0; g_sums[2] = 0.0; g_sums[3] = 0.0;
        g_minbits = 0;   // biased encoding: 0 == +inf
        g_maxbits = 0;
        g_bar1 = 0u;
        g_bar2 = 0u;
    }
    for (int i = tid; i < FB; i += NTHR) g_fhist[i] = 0u;
    // no sync needed: kernel-exit makes all writes visible to the next launch
}

extern "C" void kernel_launch(void* const* d_in, const int* in_sizes, int n_in,
                              void* d_out, int out_size) {
    const float4* in = (const float4*)d_in[0];
    const float4* Rp = (const float4*)d_in[1];
    const float4* Lp = (const float4*)d_in[2];
    (void)in_sizes; (void)n_in; (void)out_size;

    cudaFuncSetAttribute(kmain, cudaFuncAttributeMaxDynamicSharedMemorySize, SMEM_BYTES);

    kmain<<<NCTA, NTHR, SMEM_BYTES>>>(in, Rp, Lp, (float*)d_out);
}

// round 17
// speedup vs baseline: 1.0694x; 1.0694x over previous
#include <cuda_runtime.h>
#include <cuda_fp16.h>

#define HH 2048
#define WW 2048
#define HWN (HH*WW)
#define W4 (WW/4)
#define HW4 (HWN/4)
#define NCTA 296
#define NTHR 256
#define HALFW 256           // float4 columns per half-row
#define FB 2048

// dyn smem: s_im 28672 + s_rm 28672 + s_ch 1024 + s_cdf 1024 + s_fh 8192 = 67584B (x2 CTA/SM = 132KB)
#define SMEM_BYTES (14*HALFW*8*2 + 1024 + 1024 + FB*4)

__device__ double g_sums[4];
__device__ unsigned int g_fhist[FB];
__device__ int g_minbits;          // biased: rest state 0 == +inf
__device__ int g_maxbits;
__device__ unsigned int g_bar1;
__device__ unsigned int g_bar2;
// Invariant: every launch leaves all globals zeroed (self-reset at the end).

__device__ __forceinline__ int q8(float x) {
    return __float2int_rd(__saturatef(x) * 255.0f);
}
__device__ __forceinline__ int grayi(int q0, int q1, int q2) {
    return (19595 * q0 + 38470 * q1 + 7471 * q2 + 32768) >> 16;
}
__device__ __forceinline__ float eLUT(int i) {          // == old s_lut[i], bit-identical
    return __expf((float)i * (-10.0f / 255.0f));
}
__device__ __forceinline__ unsigned packh2(float a, float b) {
    __half2 h = __floats2half2_rn(a, b);
    return *reinterpret_cast<unsigned*>(&h);
}
__device__ __forceinline__ float2 unpackh2(unsigned u) {
    __half2 h = *reinterpret_cast<__half2*>(&u);
    return __half22float2(h);
}

__device__ __forceinline__ float interp1p(float x, float gmin, float scale, const float2* cdfp) {
    float u = fmaxf((x - gmin) * scale, 0.0f);
    int k = min((int)u, 255);
    float2 p = cdfp[k];
    return fmaf(p.y - p.x, u - (float)k, p.x);
}

struct Row { float4 a0, a1, a2, b0, b1, b2, lv; };

__device__ __forceinline__ Row load_row(const float4* __restrict__ in,
                                        const float4* __restrict__ Rp,
                                        const float4* __restrict__ Lp, int idx) {
    Row r;
    r.a0 = __ldcs(&in[idx]); r.a1 = __ldcs(&in[idx + HW4]); r.a2 = __ldcs(&in[idx + 2 * HW4]);
    r.b0 = __ldcs(&Rp[idx]); r.b1 = __ldcs(&Rp[idx + HW4]); r.b2 = __ldcs(&Rp[idx + 2 * HW4]);
    r.lv = __ldcs(&Lp[idx]);
    return r;
}

__global__ __launch_bounds__(NTHR, 2) void kmain(const float4* __restrict__ in,
                                                 const float4* __restrict__ Rp,
                                                 const float4* __restrict__ Lp,
                                                 float* __restrict__ out) {
    extern __shared__ char sm[];
    uint2*    s_im  = (uint2*)sm;
    uint2*    s_rm  = (uint2*)(sm + 14*HALFW*8);
    unsigned* s_ch  = (unsigned*)(sm + 14*HALFW*16);
    float*    s_cdf = (float*)(sm + 14*HALFW*16 + 1024);
    unsigned* s_fh  = (unsigned*)(sm + 14*HALFW*16 + 2048);
    float2*   s_cdfp = (float2*)s_fh;
    __shared__ double redd[3][8];
    __shared__ float  redf[2][8];

    const int tid = threadIdx.x;
    const int cta = blockIdx.x;
    const int sb  = cta >> 1;           // row slab 0..147
    const int ch  = cta & 1;            // column half

    // slabs: 0..123 -> 14 rows, 124..147 -> 13 rows (124*14 + 24*13 = 2048)
    int nr, r0;
    if (sb < 124) { nr = 14; r0 = sb * 14; }
    else          { nr = 13; r0 = 1736 + (sb - 124) * 13; }

    for (int i = tid; i < FB; i += NTHR) s_fh[i] = 0u;
    __syncthreads();

    // ---------------- Phase 1: depth-1 pipelined streaming ----------------
    const int col = ch * HALFW + tid;
    int gPx, gPy, gPz, gPw;
    float4 lP;
    if (r0 == 0) {
        gPx = gPy = gPz = gPw = 0;
        lP = make_float4(0.f, 0.f, 0.f, 0.f);
    } else {
        int idx = (r0 - 1) * W4 + col;
        float4 b0 = __ldcs(&Rp[idx]), b1 = __ldcs(&Rp[idx + HW4]), b2 = __ldcs(&Rp[idx + 2 * HW4]);
        gPx = grayi(q8(b0.x), q8(b1.x), q8(b2.x));
        gPy = grayi(q8(b0.y), q8(b1.y), q8(b2.y));
        gPz = grayi(q8(b0.z), q8(b1.z), q8(b2.z));
        gPw = grayi(q8(b0.w), q8(b1.w), q8(b2.w));
        lP = __ldcs(&Lp[idx]);
    }

    float sRec = 0.f, sIs = 0.f;
    int   sRsI = 0;
    float vmin = 3.0f, vmax = -1.0f;

    Row cur = load_row(in, Rp, Lp, r0 * W4 + col);

    auto body = [&](const Row& r, int rr) {
        // recon: balanced tree (shorter FADD critical path)
        float t0 = fabsf(r.b0.x * r.lv.x - r.a0.x) + fabsf(r.b0.y * r.lv.y - r.a0.y);
        float t1 = fabsf(r.b0.z * r.lv.z - r.a0.z) + fabsf(r.b0.w * r.lv.w - r.a0.w);
        float t2 = fabsf(r.b1.x * r.lv.x - r.a1.x) + fabsf(r.b1.y * r.lv.y - r.a1.y);
        float t3 = fabsf(r.b1.z * r.lv.z - r.a1.z) + fabsf(r.b1.w * r.lv.w - r.a1.w);
        float t4 = fabsf(r.b2.x * r.lv.x - r.a2.x) + fabsf(r.b2.y * r.lv.y - r.a2.y);
        float t5 = fabsf(r.b2.z * r.lv.z - r.a2.z) + fabsf(r.b2.w * r.lv.w - r.a2.w);
        sRec += ((t0 + t1) + (t2 + t3)) + (t4 + t5);

        float imx = fmaxf(r.a0.x, fmaxf(r.a1.x, r.a2.x));
        float imy = fmaxf(r.a0.y, fmaxf(r.a1.y, r.a2.y));
        float imz = fmaxf(r.a0.z, fmaxf(r.a1.z, r.a2.z));
        float imw = fmaxf(r.a0.w, fmaxf(r.a1.w, r.a2.w));
        float rmx = fmaxf(r.b0.x, fmaxf(r.b1.x, r.b2.x));
        float rmy = fmaxf(r.b0.y, fmaxf(r.b1.y, r.b2.y));
        float rmz = fmaxf(r.b0.z, fmaxf(r.b1.z, r.b2.z));
        float rmw = fmaxf(r.b0.w, fmaxf(r.b1.w, r.b2.w));

        int li = rr * HALFW + tid;
        s_im[li] = make_uint2(packh2(imx, imy), packh2(imz, imw));
        s_rm[li] = make_uint2(packh2(rmx, rmy), packh2(rmz, rmw));

        vmin = fminf(vmin, fminf(fminf(imx, imy), fminf(imz, imw)));
        vmax = fmaxf(vmax, fmaxf(fmaxf(imx, imy), fmaxf(imz, imw)));

        atomicAdd(&s_fh[min(FB - 1, (int)(imx * (float)FB))], 1u);
        atomicAdd(&s_fh[min(FB - 1, (int)(imy * (float)FB))], 1u);
        atomicAdd(&s_fh[min(FB - 1, (int)(imz * (float)FB))], 1u);
        atomicAdd(&s_fh[min(FB - 1, (int)(imw * (float)FB))], 1u);

        int gx = grayi(q8(r.b0.x), q8(r.b1.x), q8(r.b2.x));
        int gy = grayi(q8(r.b0.y), q8(r.b1.y), q8(r.b2.y));
        int gz = grayi(q8(r.b0.z), q8(r.b1.z), q8(r.b2.z));
        int gw = grayi(q8(r.b0.w), q8(r.b1.w), q8(r.b2.w));

        int dgx = abs(gx - gPx), dgy = abs(gy - gPy);
        int dgz = abs(gz - gPz), dgw = abs(gw - gPw);
        sRsI += (dgx + dgy) + (dgz + dgw) + 2 * ((gx + gy) + (gz + gw));

        // ismooth via MUFU (off the LSU pipe); balanced tree
        float u0 = fmaf(2.0f * fabsf(r.lv.x), eLUT(gx), fabsf(r.lv.x - lP.x) * eLUT(dgx));
        float u1 = fmaf(2.0f * fabsf(r.lv.y), eLUT(gy), fabsf(r.lv.y - lP.y) * eLUT(dgy));
        float u2 = fmaf(2.0f * fabsf(r.lv.z), eLUT(gz), fabsf(r.lv.z - lP.z) * eLUT(dgz));
        float u3 = fmaf(2.0f * fabsf(r.lv.w), eLUT(gw), fabsf(r.lv.w - lP.w) * eLUT(dgw));
        sIs += (u0 + u1) + (u2 + u3);

        gPx = gx; gPy = gy; gPz = gz; gPw = gw;
        lP = r.lv;
    };

    #pragma unroll 1
    for (int rr = 0; rr < nr - 1; rr++) {
        Row nxt = load_row(in, Rp, Lp, (r0 + rr + 1) * W4 + col);
        body(cur, rr);
        cur = nxt;
    }
    body(cur, nr - 1);

    if (r0 + nr == HH) {   // bottom padded edge
        sRsI += (gPx + gPy) + (gPz + gPw);
        sIs  += (fabsf(lP.x) * eLUT(gPx) + fabsf(lP.y) * eLUT(gPy))
              + (fabsf(lP.z) * eLUT(gPz) + fabsf(lP.w) * eLUT(gPw));
    }

    __syncthreads();
    for (int i = tid; i < FB; i += NTHR) {
        unsigned c = s_fh[i];
        if (c) atomicAdd(&g_fhist[i], c);
    }

    // block reduce (8 warps)
    double dRec = (double)sRec, dIs = (double)sIs;
    int    iRs = sRsI;
    const unsigned m = 0xffffffffu;
    for (int o = 16; o; o >>= 1) {
        dRec += __shfl_down_sync(m, dRec, o);
        dIs  += __shfl_down_sync(m, dIs,  o);
        iRs  += __shfl_down_sync(m, iRs,  o);
        vmin = fminf(vmin, __shfl_down_sync(m, vmin, o));
        vmax = fmaxf(vmax, __shfl_down_sync(m, vmax, o));
    }
    int lane = tid & 31, wid = tid >> 5;
    if (lane == 0) {
        redd[0][wid] = dRec; redd[1][wid] = (double)iRs; redd[2][wid] = dIs;
        redf[0][wid] = vmin; redf[1][wid] = vmax;
    }
    __syncthreads();
    if (wid == 0) {
        double dRs;
        dRec = (lane < 8) ? redd[0][lane] : 0.0;
        dRs  = (lane < 8) ? redd[1][lane] : 0.0;
        dIs  = (lane < 8) ? redd[2][lane] : 0.0;
        vmin = (lane < 8) ? redf[0][lane] : 3.0f;
        vmax = (lane < 8) ? redf[1][lane] : -1.0f;
        for (int o = 4; o; o >>= 1) {
            dRec += __shfl_down_sync(m, dRec, o);
            dRs  += __shfl_down_sync(m, dRs,  o);
            dIs  += __shfl_down_sync(m, dIs,  o);
            vmin = fminf(vmin, __shfl_down_sync(m, vmin, o));
            vmax = fmaxf(vmax, __shfl_down_sync(m, vmax, o));
        }
        if (lane == 0) {
            atomicAdd(&g_sums[0], dRec);
            atomicAdd(&g_sums[1], dRs);
            atomicAdd(&g_sums[2], dIs);
            atomicMin(&g_minbits, __float_as_int(vmin) - 0x7F800000);  // biased
            atomicMax(&g_maxbits, __float_as_int(vmax));
        }
    }

    // ---- grid barrier 1 ----
    __syncthreads();
    if (tid == 0) {
        __threadfence();
        atomicAdd(&g_bar1, 1u);
        while (*(volatile unsigned*)&g_bar1 < NCTA) { }
    }
    __syncthreads();
    __threadfence();

    // ---------------- Phase 3: rebin + cdf + interp + eq-sum ----------------
    const float gmin = __int_as_float(__ldcg(&g_minbits) + 0x7F800000);
    const float gmax = __int_as_float(__ldcg(&g_maxbits));
    const float scale = 256.0f / (gmax - gmin);

    s_ch[tid] = 0u;
    __syncthreads();
    for (int f = tid; f < FB; f += NTHR) {
        unsigned c = __ldcg(&g_fhist[f]);
        if (c) {
            float center = ((float)f + 0.5f) * (1.0f / (float)FB);
            int k = min(255, max(0, (int)((center - gmin) * scale)));
            atomicAdd(&s_ch[k], c);
        }
    }
    __syncthreads();

    s_cdf[tid] = (float)s_ch[tid];
    __syncthreads();
    for (int off = 1; off < 256; off <<= 1) {
        float t = (tid >= off) ? s_cdf[tid - off] : 0.0f;
        __syncthreads();
        s_cdf[tid] += t;
        __syncthreads();
    }
    float norm = s_cdf[255];
    __syncthreads();
    s_cdf[tid] = s_cdf[tid] / norm;
    __syncthreads();
    {
        float cc0 = s_cdf[tid];
        float cc1 = (tid < 255) ? s_cdf[tid + 1] : cc0;
        s_cdfp[tid] = make_float2(cc0, cc1);
    }
    __syncthreads();

    const int nelem = nr * HALFW;
    float sEq = 0.f;
    for (int i = tid; i < nelem; i += NTHR) {
        uint2 u = s_im[i];
        uint2 ru = s_rm[i];
        float2 v0 = unpackh2(u.x), v1 = unpackh2(u.y);
        float2 r0f = unpackh2(ru.x), r1f = unpackh2(ru.y);
        sEq += (fabsf(r0f.x - interp1p(v0.x, gmin, scale, s_cdfp))
              + fabsf(r0f.y - interp1p(v0.y, gmin, scale, s_cdfp)))
             + (fabsf(r1f.x - interp1p(v1.x, gmin, scale, s_cdfp))
              + fabsf(r1f.y - interp1p(v1.y, gmin, scale, s_cdfp)));
    }
    double dEq = (double)sEq;
    for (int o = 16; o; o >>= 1) dEq += __shfl_down_sync(m, dEq, o);
    if (lane == 0) redd[0][wid] = dEq;
    __syncthreads();
    if (wid == 0) {
        dEq = (lane < 8) ? redd[0][lane] : 0.0;
        for (int o = 4; o; o >>= 1) dEq += __shfl_down_sync(m, dEq, o);
        if (lane == 0) atomicAdd(&g_sums[3], dEq);
    }

    // ---- finish barrier: others arrive + exit, CTA0 polls ----
    __syncthreads();
    if (tid == 0) {
        __threadfence();
        atomicAdd(&g_bar2, 1u);
    }
    if (cta != 0) return;

    if (tid == 0) {
        while (*(volatile unsigned*)&g_bar2 < NCTA) { }
    }
    __syncthreads();
    __threadfence();

    // combine + full reset for next graph replay
    if (tid == 0) {
        double recon = __ldcg(&g_sums[0]) / (3.0 * (double)HWN);
        double denom = 2.0 * (double)(HH + 1) * (double)(WW + 2);
        double rs = __ldcg(&g_sums[1]) / (255.0 * denom);
        double is = __ldcg(&g_sums[2]) / denom;
        double eq = __ldcg(&g_sums[3]) / (double)HWN;
        out[0] = (float)(recon + 0.1 * is + 0.1 * eq + 0.01 * rs);
        g_sums[0] = 0.0; g_sums[1] = 0.0; g_sums[2] = 0.0; g_sums[3] = 0.0;
        g_minbits = 0;
        g_maxbits = 0;
        g_bar1 = 0u;
        g_bar2 = 0u;
    }
    for (int i = tid; i < FB; i += NTHR) g_fhist[i] = 0u;
}

extern "C" void kernel_launch(void* const* d_in, const int* in_sizes, int n_in,
                              void* d_out, int out_size) {
    const float4* in = (const float4*)d_in[0];
    const float4* Rp = (const float4*)d_in[1];
    const float4* Lp = (const float4*)d_in[2];
    (void)in_sizes; (void)n_in; (void)out_size;

    cudaFuncSetAttribute(kmain, cudaFuncAttributeMaxDynamicSharedMemorySize, SMEM_BYTES);

    kmain<<<NCTA, NTHR, SMEM_BYTES>>>(in, Rp, Lp, (float*)d_out);
}